// round 13
// baseline (speedup 1.0000x reference)
#include <cuda_runtime.h>
#include <cuda_bf16.h>

// Problem shape (fixed by the dataset)
#define B_DIM 16
#define S_DIM 2048
#define D_DIM 256
#define ROWS  (B_DIM * S_DIM)          // 32768
#define QUADS (ROWS / 4)               // 8192
#define P_ASEM 0.6f
#define Q_ASEM 0.4f
#define MASK_FILL 1e-9f

// Scratch (no cudaMalloc allowed). All fully overwritten each launch.
__device__ float    g_si[ROWS];    // si + bias folded in (unmasked rows only)
__device__ float    g_sj[ROWS];
__device__ unsigned g_rows[ROWS];  // SORTED compacted unmasked row indices
__device__ unsigned g_count;       // number of unmasked rows

// ---------------------------------------------------------------------------
// Kernel 1 (proj_fill_scan): QUADS+1 blocks of 256 threads.
//   blocks 0..QUADS-1 : quad per block —
//       warps 0..3: dual dot products for their row (if unmasked)
//       all threads: MASK_FILL output writes for masked rows (134 MB)
//   block QUADS       : deterministic mask prefix-scan -> sorted g_rows, g_count
// ---------------------------------------------------------------------------
__global__ __launch_bounds__(256) void proj_fill_scan_kernel(
        const float* __restrict__ x,
        const int*   __restrict__ mask,
        const float* __restrict__ W,
        const float* __restrict__ bias,
        float4*      __restrict__ out4) {
    const unsigned tid = threadIdx.x;

    // ---------------- scan block: sorted compaction ----------------
    if (blockIdx.x == QUADS) {
        __shared__ unsigned s[256];
        const int4* m4 = reinterpret_cast<const int4*>(mask);

        // pass 1: per-thread count over rows [128*tid, 128*tid+128)
        unsigned c = 0;
#pragma unroll 8
        for (int i = 0; i < 32; ++i) {
            int4 v = __ldg(&m4[tid * 32 + i]);
            c += (unsigned)(v.x + v.y + v.z + v.w);   // mask values are 0/1
        }
        s[tid] = c;
        __syncthreads();

        // inclusive Hillis-Steele scan over 256 thread counts
        for (int off = 1; off < 256; off <<= 1) {
            unsigned v = (tid >= (unsigned)off) ? s[tid - off] : 0u;
            __syncthreads();
            s[tid] += v;
            __syncthreads();
        }

        if (tid == 255) g_count = s[255];

        // pass 2: write sorted compacted indices
        unsigned pos = (tid == 0) ? 0u : s[tid - 1];
        const int rbase = (int)tid * 128;
        for (int i = 0; i < 128; ++i) {
            if (__ldg(&mask[rbase + i])) g_rows[pos++] = (unsigned)(rbase + i);
        }
        return;
    }

    // ---------------- proj + fill blocks ----------------
    const int      lane = tid & 31;
    const int      wid  = tid >> 5;
    const unsigned row0 = blockIdx.x << 2;
    const unsigned base = row0 << 9;

    int mi[4];
#pragma unroll
    for (int r = 0; r < 4; ++r) mi[r] = __ldg(&mask[row0 + r]);

    // projections for unmasked rows (warps 0..3, one row each)
    if (wid < 4 && mi[wid]) {
        const int row = row0 + wid;
        const float4* x4  = reinterpret_cast<const float4*>(x) + (long)row * (D_DIM / 4);
        const float4* Wi4 = reinterpret_cast<const float4*>(W);            // W[0:256]
        const float4* Wj4 = reinterpret_cast<const float4*>(W + D_DIM);    // W[256:512]

        float4 xv0 = x4[lane];
        float4 xv1 = x4[lane + 32];
        float4 wi0 = __ldg(&Wi4[lane]);
        float4 wi1 = __ldg(&Wi4[lane + 32]);
        float4 wj0 = __ldg(&Wj4[lane]);
        float4 wj1 = __ldg(&Wj4[lane + 32]);

        float si = 0.f, sj = 0.f;
        si = fmaf(xv0.x, wi0.x, si); si = fmaf(xv0.y, wi0.y, si);
        si = fmaf(xv0.z, wi0.z, si); si = fmaf(xv0.w, wi0.w, si);
        si = fmaf(xv1.x, wi1.x, si); si = fmaf(xv1.y, wi1.y, si);
        si = fmaf(xv1.z, wi1.z, si); si = fmaf(xv1.w, wi1.w, si);
        sj = fmaf(xv0.x, wj0.x, sj); sj = fmaf(xv0.y, wj0.y, sj);
        sj = fmaf(xv0.z, wj0.z, sj); sj = fmaf(xv0.w, wj0.w, sj);
        sj = fmaf(xv1.x, wj1.x, sj); sj = fmaf(xv1.y, wj1.y, sj);
        sj = fmaf(xv1.z, wj1.z, sj); sj = fmaf(xv1.w, wj1.w, sj);

#pragma unroll
        for (int off = 16; off > 0; off >>= 1) {
            si += __shfl_down_sync(0xFFFFFFFFu, si, off);
            sj += __shfl_down_sync(0xFFFFFFFFu, sj, off);
        }
        if (lane == 0) {
            g_si[row] = si + __ldg(bias);
            g_sj[row] = sj;
        }
    }

    // fill writes for masked rows (all 256 threads)
    const float4 fill = make_float4(MASK_FILL, MASK_FILL, MASK_FILL, MASK_FILL);
#pragma unroll
    for (int r = 0; r < 4; ++r) {
        if (!mi[r]) {
            const unsigned o = base + (r << 9) + tid;
            __stcs(&out4[o], fill);
            __stcs(&out4[o + 256], fill);
        }
    }
}

// ---------------------------------------------------------------------------
// Kernel 2 (blend): DENSE over SORTED compacted rows — block i handles
// compacted rows 2i, 2i+1 (adjacent blocks -> adjacent memory). 4 float4
// loads + 4 stores per thread, MLP=4. Worst-case grid; excess blocks exit.
// ---------------------------------------------------------------------------
__device__ __forceinline__ float sig_blend(float si, float sjv, int m, float a) {
    float z = si + sjv;
    float s = __fdividef(1.f, 1.f + __expf(-z));
    return m ? fmaf(P_ASEM, s, Q_ASEM * a) : MASK_FILL;
}

__global__ __launch_bounds__(256) void blend_kernel(const float4* __restrict__ adj4,
                                                    const int*    __restrict__ mask,
                                                    float4*       __restrict__ out4) {
    const unsigned tid = threadIdx.x;
    const unsigned cnt = g_count;
    const unsigned i0  = blockIdx.x << 1;
    if (i0 >= cnt) return;

    const unsigned row0  = g_rows[i0];
    const bool     have1 = (i0 + 1 < cnt);
    const unsigned row1  = have1 ? g_rows[i0 + 1] : row0;

    const unsigned o0 = (row0 << 9) + tid;
    const unsigned o1 = (row1 << 9) + tid;

    // all adj loads up front (4 independent LDG.128 per thread)
    float4 a0A = __ldcs(&adj4[o0]);
    float4 a0B = __ldcs(&adj4[o0 + 256]);
    float4 a1A, a1B;
    if (have1) {
        a1A = __ldcs(&adj4[o1]);
        a1B = __ldcs(&adj4[o1 + 256]);
    }

    const float4* sj4 = reinterpret_cast<const float4*>(g_sj);
    const int4*   mj4 = reinterpret_cast<const int4*>(mask);
    const unsigned c0 = ((row0 >> 11) << 9) + tid;
    const unsigned c1 = ((row1 >> 11) << 9) + tid;

    const float4 sj0A = __ldg(&sj4[c0]);
    const float4 sj0B = __ldg(&sj4[c0 + 256]);
    const int4   m0A  = __ldg(&mj4[c0]);
    const int4   m0B  = __ldg(&mj4[c0 + 256]);

    const float si0 = g_si[row0];

    float4 out;
    out.x = sig_blend(si0, sj0A.x, m0A.x, a0A.x);
    out.y = sig_blend(si0, sj0A.y, m0A.y, a0A.y);
    out.z = sig_blend(si0, sj0A.z, m0A.z, a0A.z);
    out.w = sig_blend(si0, sj0A.w, m0A.w, a0A.w);
    __stcs(&out4[o0], out);

    out.x = sig_blend(si0, sj0B.x, m0B.x, a0B.x);
    out.y = sig_blend(si0, sj0B.y, m0B.y, a0B.y);
    out.z = sig_blend(si0, sj0B.z, m0B.z, a0B.z);
    out.w = sig_blend(si0, sj0B.w, m0B.w, a0B.w);
    __stcs(&out4[o0 + 256], out);

    if (have1) {
        const float4 sj1A = __ldg(&sj4[c1]);
        const float4 sj1B = __ldg(&sj4[c1 + 256]);
        const int4   m1A  = __ldg(&mj4[c1]);
        const int4   m1B  = __ldg(&mj4[c1 + 256]);
        const float  si1  = g_si[row1];

        out.x = sig_blend(si1, sj1A.x, m1A.x, a1A.x);
        out.y = sig_blend(si1, sj1A.y, m1A.y, a1A.y);
        out.z = sig_blend(si1, sj1A.z, m1A.z, a1A.z);
        out.w = sig_blend(si1, sj1A.w, m1A.w, a1A.w);
        __stcs(&out4[o1], out);

        out.x = sig_blend(si1, sj1B.x, m1B.x, a1B.x);
        out.y = sig_blend(si1, sj1B.y, m1B.y, a1B.y);
        out.z = sig_blend(si1, sj1B.z, m1B.z, a1B.z);
        out.w = sig_blend(si1, sj1B.w, m1B.w, a1B.w);
        __stcs(&out4[o1 + 256], out);
    }
}

// ---------------------------------------------------------------------------
// Launch
// Inputs (metadata order): 0:x [16,2048,256] f32, 1:adj [16,2048,2048] f32,
//                          2:mask [16,2048] i32, 3:W [1,512] f32, 4:b [1] f32
// Output: [16,2048,2048] f32
// ---------------------------------------------------------------------------
extern "C" void kernel_launch(void* const* d_in, const int* in_sizes, int n_in,
                              void* d_out, int out_size) {
    const float* x    = (const float*)d_in[0];
    const float* adj  = (const float*)d_in[1];
    const int*   mask = (const int*)d_in[2];
    const float* W    = (const float*)d_in[3];
    const float* bias = (const float*)d_in[4];
    float4* out = (float4*)d_out;

    // Kernel 1: projections + masked-row fill + sorted compaction scan
    proj_fill_scan_kernel<<<QUADS + 1, 256>>>(x, mask, W, bias, out);

    // Kernel 2: dense blend over sorted compacted rows, 2 rows/block
    blend_kernel<<<ROWS / 2, 256>>>(reinterpret_cast<const float4*>(adj),
                                    mask, out);
}

// round 14
// speedup vs baseline: 1.4394x; 1.4394x over previous
#include <cuda_runtime.h>
#include <cuda_bf16.h>

// Problem shape (fixed by the dataset)
#define B_DIM 16
#define S_DIM 2048
#define D_DIM 256
#define ROWS  (B_DIM * S_DIM)          // 32768
#define P_ASEM 0.6f
#define Q_ASEM 0.4f
#define MASK_FILL 1e-9f

// Scratch for projected scores (no cudaMalloc allowed)
__device__ float g_si[ROWS];  // si + bias folded in
__device__ float g_sj[ROWS];

// ---------------------------------------------------------------------------
// Kernel 1: dual dot products, 4 rows per warp, masked-row skip (R10 version,
// proven). Rows with mask==0 are never consumed downstream -> skip entirely.
// ---------------------------------------------------------------------------
#define PROJ_RPW 4   // rows per warp

__global__ __launch_bounds__(256) void proj_kernel(const float* __restrict__ x,
                                                   const int*   __restrict__ mask,
                                                   const float* __restrict__ W,
                                                   const float* __restrict__ bias) {
    const int warp = blockIdx.x * (blockDim.x >> 5) + (threadIdx.x >> 5);
    const int lane = threadIdx.x & 31;
    const int row0 = warp * PROJ_RPW;

    int mrow[PROJ_RPW];
#pragma unroll
    for (int r = 0; r < PROJ_RPW; ++r) mrow[r] = __ldg(&mask[row0 + r]);

    const float4* Wi4 = reinterpret_cast<const float4*>(W);            // W[0:256]
    const float4* Wj4 = reinterpret_cast<const float4*>(W + D_DIM);    // W[256:512]

    float4 xv[PROJ_RPW][2];
#pragma unroll
    for (int r = 0; r < PROJ_RPW; ++r) {
        if (mrow[r]) {
            const float4* x4 = reinterpret_cast<const float4*>(x) +
                               (long)(row0 + r) * (D_DIM / 4);
            xv[r][0] = x4[lane];
            xv[r][1] = x4[lane + 32];
        }
    }

    const float4 wi0 = __ldg(&Wi4[lane]);
    const float4 wi1 = __ldg(&Wi4[lane + 32]);
    const float4 wj0 = __ldg(&Wj4[lane]);
    const float4 wj1 = __ldg(&Wj4[lane + 32]);

    float si[PROJ_RPW], sj[PROJ_RPW];
#pragma unroll
    for (int r = 0; r < PROJ_RPW; ++r) {
        if (!mrow[r]) { si[r] = 0.f; sj[r] = 0.f; continue; }
        float a = 0.f, b2 = 0.f;
        a = fmaf(xv[r][0].x, wi0.x, a); a = fmaf(xv[r][0].y, wi0.y, a);
        a = fmaf(xv[r][0].z, wi0.z, a); a = fmaf(xv[r][0].w, wi0.w, a);
        a = fmaf(xv[r][1].x, wi1.x, a); a = fmaf(xv[r][1].y, wi1.y, a);
        a = fmaf(xv[r][1].z, wi1.z, a); a = fmaf(xv[r][1].w, wi1.w, a);
        b2 = fmaf(xv[r][0].x, wj0.x, b2); b2 = fmaf(xv[r][0].y, wj0.y, b2);
        b2 = fmaf(xv[r][0].z, wj0.z, b2); b2 = fmaf(xv[r][0].w, wj0.w, b2);
        b2 = fmaf(xv[r][1].x, wj1.x, b2); b2 = fmaf(xv[r][1].y, wj1.y, b2);
        b2 = fmaf(xv[r][1].z, wj1.z, b2); b2 = fmaf(xv[r][1].w, wj1.w, b2);
        si[r] = a; sj[r] = b2;
    }

#pragma unroll
    for (int off = 16; off > 0; off >>= 1) {
#pragma unroll
        for (int r = 0; r < PROJ_RPW; ++r) {
            if (mrow[r]) {
                si[r] += __shfl_down_sync(0xFFFFFFFFu, si[r], off);
                sj[r] += __shfl_down_sync(0xFFFFFFFFu, sj[r], off);
            }
        }
    }
    if (lane == 0) {
        const float bv = __ldg(bias);
#pragma unroll
        for (int r = 0; r < PROJ_RPW; ++r) {
            if (mrow[r]) {
                g_si[row0 + r] = si[r] + bv;
                g_sj[row0 + r] = sj[r];
            }
        }
    }
}

// ---------------------------------------------------------------------------
// Kernel 2: R6 fuse body at 512 threads/block — each thread covers exactly
// ONE float4 per row (tid spans the full 512-float4 row), so per-thread work
// is 4 adj loads + 4 stores + ONE sj/mask column vector. Same ordering as the
// proven body: adj loads up front, fill stores in the per-row loop.
// ---------------------------------------------------------------------------
#define RPB 4   // rows per block

__device__ __forceinline__ float sig_blend(float si, float sjv, int m, float a) {
    float z = si + sjv;
    float s = __fdividef(1.f, 1.f + __expf(-z));
    return m ? fmaf(P_ASEM, s, Q_ASEM * a) : MASK_FILL;
}

__global__ __launch_bounds__(512) void fuse_kernel(const float4* __restrict__ adj4,
                                                   const int*    __restrict__ mask,
                                                   float4*       __restrict__ out4) {
    const unsigned tid   = threadIdx.x;                      // 0..511
    const unsigned row0  = blockIdx.x * RPB;                 // rows row0..row0+3 (same batch)
    const unsigned base  = (row0 << 9) + tid;                // float4 idx of row0[tid]
    const unsigned cbase = ((row0 >> 11) << 9) + tid;        // sj/mask col float4 index

    // per-row masks (uniform across block for each row)
    int mi[RPB];
#pragma unroll
    for (int r = 0; r < RPB; ++r) mi[r] = mask[row0 + r];

    // issue ALL adj loads for unmasked rows up front (predicated, independent)
    float4 av[RPB];
#pragma unroll
    for (int r = 0; r < RPB; ++r) {
        if (mi[r]) av[r] = __ldcs(&adj4[base + (r << 9)]);
    }

    // column vectors: shared by all RPB rows, one load each
    const float4* sj4 = reinterpret_cast<const float4*>(g_sj);
    const int4*   mj4 = reinterpret_cast<const int4*>(mask);
    const float4 sjv = __ldg(&sj4[cbase]);
    const int4   mjv = __ldg(&mj4[cbase]);

#pragma unroll
    for (int r = 0; r < RPB; ++r) {
        const unsigned o = base + (r << 9);
        if (mi[r]) {
            const float si = g_si[row0 + r];
            float4 out;
            out.x = sig_blend(si, sjv.x, mjv.x, av[r].x);
            out.y = sig_blend(si, sjv.y, mjv.y, av[r].y);
            out.z = sig_blend(si, sjv.z, mjv.z, av[r].z);
            out.w = sig_blend(si, sjv.w, mjv.w, av[r].w);
            __stcs(&out4[o], out);
        } else {
            const float4 fill = make_float4(MASK_FILL, MASK_FILL, MASK_FILL, MASK_FILL);
            __stcs(&out4[o], fill);
        }
    }
}

// ---------------------------------------------------------------------------
// Launch
// Inputs (metadata order): 0:x [16,2048,256] f32, 1:adj [16,2048,2048] f32,
//                          2:mask [16,2048] i32, 3:W [1,512] f32, 4:b [1] f32
// Output: [16,2048,2048] f32
// ---------------------------------------------------------------------------
extern "C" void kernel_launch(void* const* d_in, const int* in_sizes, int n_in,
                              void* d_out, int out_size) {
    const float* x    = (const float*)d_in[0];
    const float* adj  = (const float*)d_in[1];
    const int*   mask = (const int*)d_in[2];
    const float* W    = (const float*)d_in[3];
    const float* bias = (const float*)d_in[4];
    float* out = (float*)d_out;

    // Kernel 1: 4 rows/warp, 8 warps/block -> 32 rows/block -> 1024 blocks
    proj_kernel<<<ROWS / (PROJ_RPW * 8), 256>>>(x, mask, W, bias);

    // Kernel 2: one block per 4 output rows -> 8192 blocks of 512 threads
    fuse_kernel<<<ROWS / RPB, 512>>>(reinterpret_cast<const float4*>(adj),
                                     mask,
                                     reinterpret_cast<float4*>(out));
}